// round 12
// baseline (speedup 1.0000x reference)
#include <cuda_runtime.h>
#include <cuda_fp16.h>
#include <cstdint>

#define NN   4096
#define FIN  256
#define FOUT 256
#define NH   4
#define DD   64
#define ALPHA 0.2f
#define NZ   4
#define NTILES (NN / NZ / 64)   // 16

// ---------------- device scratch (no allocs allowed) ----------------
__device__ float    g_h [NN * FOUT];
__device__ __half   g_hf[NN * FOUT];
__device__ unsigned g_adjbits[NN * (NN / 32)];
__device__ float    g_A[NH * NN];
__device__ float    g_B[NH * NN];
__device__ float2   g_e12[NH * NN];
__device__ unsigned g_emaxu[NH];
__device__ float    g_atts[NZ * NN * FOUT];
__device__ float    g_den[NZ * NH * NN];

// ---------------- helpers ----------------
__device__ __forceinline__ void cp16(uint32_t dst, const void* src) {
    asm volatile("cp.async.cg.shared.global [%0], [%1], 16;\n" :: "r"(dst), "l"(src));
}
__device__ __forceinline__ void cp8(uint32_t dst, const void* src) {
    asm volatile("cp.async.ca.shared.global [%0], [%1], 8;\n" :: "r"(dst), "l"(src));
}
__device__ __forceinline__ void cp_commit() {
    asm volatile("cp.async.commit_group;\n");
}
__device__ __forceinline__ void cp_wait0() {
    asm volatile("cp.async.wait_group 0;\n");
}
__device__ __forceinline__ void cp_wait1() {
    asm volatile("cp.async.wait_group 1;\n");
}
__device__ __forceinline__ void mma_tf32(float* d, unsigned a0, unsigned a1, unsigned a2,
                                         unsigned a3, unsigned b0, unsigned b1) {
    asm volatile(
        "mma.sync.aligned.m16n8k8.row.col.f32.tf32.tf32.f32 "
        "{%0,%1,%2,%3}, {%4,%5,%6,%7}, {%8,%9}, {%0,%1,%2,%3};\n"
        : "+f"(d[0]), "+f"(d[1]), "+f"(d[2]), "+f"(d[3])
        : "r"(a0), "r"(a1), "r"(a2), "r"(a3), "r"(b0), "r"(b1));
}
__device__ __forceinline__ void mma_f16(float* d, unsigned a0, unsigned a1, unsigned a2,
                                        unsigned a3, unsigned b0, unsigned b1) {
    asm volatile(
        "mma.sync.aligned.m16n8k16.row.col.f32.f16.f16.f32 "
        "{%0,%1,%2,%3}, {%4,%5,%6,%7}, {%8,%9}, {%0,%1,%2,%3};\n"
        : "+f"(d[0]), "+f"(d[1]), "+f"(d[2]), "+f"(d[3])
        : "r"(a0), "r"(a1), "r"(a2), "r"(a3), "r"(b0), "r"(b1));
}
__device__ __forceinline__ void ldsm_x4(unsigned& r0, unsigned& r1, unsigned& r2,
                                        unsigned& r3, uint32_t addr) {
    asm volatile("ldmatrix.sync.aligned.m8n8.x4.shared.b16 {%0,%1,%2,%3}, [%4];"
                 : "=r"(r0), "=r"(r1), "=r"(r2), "=r"(r3) : "r"(addr));
}
__device__ __forceinline__ void ldsm_x4_t(unsigned& r0, unsigned& r1, unsigned& r2,
                                          unsigned& r3, uint32_t addr) {
    asm volatile("ldmatrix.sync.aligned.m8n8.x4.trans.shared.b16 {%0,%1,%2,%3}, [%4];"
                 : "=r"(r0), "=r"(r1), "=r"(r2), "=r"(r3) : "r"(addr));
}
__device__ __forceinline__ float cvt_tf32(float x) {
    unsigned u;
    asm("cvt.rna.tf32.f32 %0, %1;" : "=r"(u) : "f"(x));
    return __uint_as_float(u);
}

// ---------------- kernel 1: pack adj int32 -> bits (+ init emax) ----------------
__global__ void pack_adj_kernel(const int* __restrict__ adj) {
    if (blockIdx.x == 0 && threadIdx.x < NH) g_emaxu[threadIdx.x] = 0u;
    int lane = threadIdx.x & 31;
    size_t gw = (size_t)(blockIdx.x * blockDim.x + threadIdx.x) >> 5;
    const int* base = adj + gw * 1024;
    unsigned myword = 0;
#pragma unroll
    for (int i = 0; i < 32; i++) {
        int v = base[i * 32 + lane];
        unsigned b = __ballot_sync(0xffffffffu, v > 0);
        if (lane == i) myword = b;
    }
    g_adjbits[gw * 32 + lane] = myword;
}

// ---------------- kernel 2: h = x @ W via tf32x3 mma ----------------
#define GXH 0
#define GXL 2304
#define GWH 4608
#define GWL 9088
#define GSM 13568

__global__ __launch_bounds__(256) void gemm_h_mma(const float* __restrict__ x,
                                                  const float* __restrict__ W) {
    extern __shared__ float gs[];
    int t = threadIdx.x;
    int m0 = blockIdx.x * 64;
    int byn0 = blockIdx.y * 128;

    int lane = t & 31, wid = t >> 5;
    int g = lane >> 2, tig = lane & 3;
    int wm0 = (wid & 3) * 16;
    int wn0l = (wid >> 2) * 64;

    int xr = t >> 2, xkc = (t & 3) * 8;
    int wkr = t >> 3, wnb = (t & 7) * 4;

    float4 xa, xb, wreg[4];
    auto ldg_tile = [&](int kt) {
        int k0 = kt * 32;
        const float4* xp = (const float4*)(x + (size_t)(m0 + xr) * FIN + k0 + xkc);
        xa = xp[0];
        xb = xp[1];
#pragma unroll
        for (int c = 0; c < 4; c++)
            wreg[c] = *(const float4*)(W + (size_t)(k0 + wkr) * FOUT + byn0 + wnb + 32 * c);
    };
    auto sts_tile = [&]() {
        float4 h, l;
        h = make_float4(cvt_tf32(xa.x), cvt_tf32(xa.y), cvt_tf32(xa.z), cvt_tf32(xa.w));
        l = make_float4(xa.x - h.x, xa.y - h.y, xa.z - h.z, xa.w - h.w);
        *(float4*)&gs[GXH + xr * 36 + xkc] = h;
        *(float4*)&gs[GXL + xr * 36 + xkc] = l;
        h = make_float4(cvt_tf32(xb.x), cvt_tf32(xb.y), cvt_tf32(xb.z), cvt_tf32(xb.w));
        l = make_float4(xb.x - h.x, xb.y - h.y, xb.z - h.z, xb.w - h.w);
        *(float4*)&gs[GXH + xr * 36 + xkc + 4] = h;
        *(float4*)&gs[GXL + xr * 36 + xkc + 4] = l;
#pragma unroll
        for (int c = 0; c < 4; c++) {
            float4 v = wreg[c];
            h = make_float4(cvt_tf32(v.x), cvt_tf32(v.y), cvt_tf32(v.z), cvt_tf32(v.w));
            l = make_float4(v.x - h.x, v.y - h.y, v.z - h.z, v.w - h.w);
            *(float4*)&gs[GWH + wkr * 140 + wnb + 32 * c] = h;
            *(float4*)&gs[GWL + wkr * 140 + wnb + 32 * c] = l;
        }
    };

    float acc[8][4] = {};
    ldg_tile(0);
    for (int kt = 0; kt < 8; kt++) {
        if (kt) __syncthreads();
        sts_tile();
        __syncthreads();
        if (kt < 7) ldg_tile(kt + 1);
#pragma unroll
        for (int ks = 0; ks < 4; ks++) {
            int k0s = ks * 8;
            unsigned ah0 = __float_as_uint(gs[GXH + (wm0 + g) * 36 + k0s + tig]);
            unsigned ah1 = __float_as_uint(gs[GXH + (wm0 + g + 8) * 36 + k0s + tig]);
            unsigned ah2 = __float_as_uint(gs[GXH + (wm0 + g) * 36 + k0s + tig + 4]);
            unsigned ah3 = __float_as_uint(gs[GXH + (wm0 + g + 8) * 36 + k0s + tig + 4]);
            unsigned al0 = __float_as_uint(gs[GXL + (wm0 + g) * 36 + k0s + tig]);
            unsigned al1 = __float_as_uint(gs[GXL + (wm0 + g + 8) * 36 + k0s + tig]);
            unsigned al2 = __float_as_uint(gs[GXL + (wm0 + g) * 36 + k0s + tig + 4]);
            unsigned al3 = __float_as_uint(gs[GXL + (wm0 + g + 8) * 36 + k0s + tig + 4]);
#pragma unroll
            for (int j = 0; j < 8; j++) {
                int bo = (k0s + tig) * 140 + wn0l + 8 * j + g;
                int bo4 = (k0s + tig + 4) * 140 + wn0l + 8 * j + g;
                unsigned bh0 = __float_as_uint(gs[GWH + bo]);
                unsigned bh1 = __float_as_uint(gs[GWH + bo4]);
                unsigned bl0 = __float_as_uint(gs[GWL + bo]);
                unsigned bl1 = __float_as_uint(gs[GWL + bo4]);
                mma_tf32(acc[j], ah0, ah1, ah2, ah3, bh0, bh1);
                mma_tf32(acc[j], ah0, ah1, ah2, ah3, bl0, bl1);
                mma_tf32(acc[j], al0, al1, al2, al3, bh0, bh1);
            }
        }
    }

    int r0 = m0 + wm0 + g, r1 = r0 + 8;
#pragma unroll
    for (int j = 0; j < 8; j++) {
        int cg = byn0 + wn0l + 8 * j + 2 * tig;
        *(float2*)(g_h + (size_t)r0 * FOUT + cg) = make_float2(acc[j][0], acc[j][1]);
        *(float2*)(g_h + (size_t)r1 * FOUT + cg) = make_float2(acc[j][2], acc[j][3]);
        *(__half2*)(g_hf + (size_t)r0 * FOUT + cg) = __floats2half2_rn(acc[j][0], acc[j][1]);
        *(__half2*)(g_hf + (size_t)r1 * FOUT + cg) = __floats2half2_rn(acc[j][2], acc[j][3]);
    }
}

// ---------------- kernel 3: si/sj dots + exp tables + head max ----------------
__global__ void prep_kernel(const float* __restrict__ a) {
    __shared__ float a_s[128];
    int t = threadIdx.x;
    if (t < 128) a_s[t] = a[t];
    __syncthreads();
    int wid  = t >> 5, lane = t & 31;
    int n    = blockIdx.x * 8 + wid;
    int head = lane >> 3;
    int sub  = lane & 7;
    const float4* hrow = (const float4*)(g_h + (size_t)n * FOUT);
    float psi = 0.f, psj = 0.f;
#pragma unroll
    for (int v = 0; v < 2; v++) {
        float4 hv = hrow[lane * 2 + v];
        int db = sub * 8 + v * 4;
        psi += hv.x * a_s[db]      + hv.y * a_s[db + 1]      + hv.z * a_s[db + 2]      + hv.w * a_s[db + 3];
        psj += hv.x * a_s[64 + db] + hv.y * a_s[64 + db + 1] + hv.z * a_s[64 + db + 2] + hv.w * a_s[64 + db + 3];
    }
#pragma unroll
    for (int off = 4; off; off >>= 1) {
        psi += __shfl_down_sync(0xffffffffu, psi, off);
        psj += __shfl_down_sync(0xffffffffu, psj, off);
    }
    if (sub == 0) {
        int idx = head * NN + n;
        float e1 = expf(psj);
        g_A[idx]   = expf(psi);
        g_B[idx]   = expf(ALPHA * psi);
        g_e12[idx] = make_float2(e1, expf(ALPHA * psj));
        atomicMax(&g_emaxu[head], __float_as_uint(e1));
    }
}

// ---------------- kernel 4: fused attention (fp16 mma, single-barrier pipeline) ----------------
// smem BYTE offsets
#define HSB    0        // H tiles, 3 buffers x 9216
#define WTB    27648    // Wt, 2 buffers x 9216
#define E12B   46080    // float2[64], 3 buffers x 512
#define ADJB   47616    // uint[128], 3 buffers x 512
#define SPB    49152    // float[256]
#define SMEMB  50176

// grid (64, NH, NZ). 256 thr, 4 CTA/SM.
__global__ __launch_bounds__(256, 4) void attn_kernel() {
    extern __shared__ char smc[];
    float* Sp = (float*)(smc + SPB);

    int t  = threadIdx.x;
    int hd = blockIdx.y;
    int n0 = blockIdx.x * 64;
    int z  = blockIdx.z;
    int mz0 = z * (NN / NZ);

    uint32_t base = (uint32_t)__cvta_generic_to_shared(smc);

    int nl = t & 63, mc = t >> 6;
    int lane = t & 31, wid = t >> 5;
    int g   = lane >> 2;
    int tig = lane & 3;
    int wn0 = (wid & 3) * 16;
    int wd0 = (wid >> 2) * 32;
    float acc[4][4] = {};
    float sacc = 0.f;

    float An = g_A[hd * NN + n0 + nl];
    float Bn = g_B[hd * NN + n0 + nl];
    {
        float E1x = __uint_as_float(g_emaxu[hd]);
        float E2x = __powf(E1x, ALPHA);
        float s = 16384.f / fmaxf(An * E1x, Bn * E2x);
        An *= s;
        Bn *= s;
    }

    int lrow = (lane & 7) + (lane & 8);
    int lhi8 = (lane >> 4) * 8;
    uint32_t a_off = (uint32_t)(wn0 + lrow) * 144u + (uint32_t)lhi8 * 2u;
    uint32_t b_rowoff = (uint32_t)lrow * 144u + (uint32_t)(wd0 + lhi8) * 2u;

    auto stage_H = [&](int mt, int b) {
        int m0 = mz0 + mt * 64;
        uint32_t hb = base + HSB + (uint32_t)b * 9216u;
#pragma unroll
        for (int r = 0; r < 2; r++) {
            int li = t + r * 256;
            int mi = li >> 3, c = li & 7;
            cp16(hb + (uint32_t)(mi * 144 + c * 16),
                 g_hf + (size_t)(m0 + mi) * FOUT + hd * DD + c * 8);
        }
    };
    auto stage_E = [&](int mt, int b) {
        int m0 = mz0 + mt * 64;
        if (t < 32)
            cp16(base + E12B + (uint32_t)b * 512u + (uint32_t)t * 16u,
                 (const char*)(g_e12 + hd * NN + m0) + t * 16);
        if (t >= 64 && t < 128) {
            int rr = t - 64;
            cp8(base + ADJB + (uint32_t)b * 512u + (uint32_t)rr * 8u,
                g_adjbits + (size_t)(n0 + rr) * (NN / 32) + (m0 >> 5));
        }
    };

    auto wgen = [&](int i) {
        int pe = i % 3;
        int wb = i & 1;
        unsigned word = ((unsigned*)(smc + ADJB + pe * 512))[nl * 2 + (mc >> 1)]
                        >> ((mc & 1) * 16);
        const float4* e4 = (const float4*)(smc + E12B + pe * 512 + mc * 128);
        unsigned wp[8];
#pragma unroll
        for (int i2 = 0; i2 < 16; i2 += 4) {
            float4 ea = e4[(i2 >> 1)];
            float4 eb = e4[(i2 >> 1) + 1];
            float w0 = fmaxf(An * ea.x, Bn * ea.y);
            float w1 = fmaxf(An * ea.z, Bn * ea.w);
            float w2 = fmaxf(An * eb.x, Bn * eb.y);
            float w3 = fmaxf(An * eb.z, Bn * eb.w);
            w0 = ((word >> (i2 + 0)) & 1u) ? w0 : 0.f;
            w1 = ((word >> (i2 + 1)) & 1u) ? w1 : 0.f;
            w2 = ((word >> (i2 + 2)) & 1u) ? w2 : 0.f;
            w3 = ((word >> (i2 + 3)) & 1u) ? w3 : 0.f;
            sacc += (w0 + w1) + (w2 + w3);
            __half2 h01 = __floats2half2_rn(w0, w1);
            __half2 h23 = __floats2half2_rn(w2, w3);
            wp[(i2 >> 1)]     = *(unsigned*)&h01;
            wp[(i2 >> 1) + 1] = *(unsigned*)&h23;
        }
        uint4* wr = (uint4*)(smc + WTB + wb * 9216 + nl * 144 + mc * 32);
        wr[0] = make_uint4(wp[0], wp[1], wp[2], wp[3]);
        wr[1] = make_uint4(wp[4], wp[5], wp[6], wp[7]);
    };

    auto mma_tile = [&](int j) {
        uint32_t ab = base + WTB + (uint32_t)(j & 1) * 9216u + a_off;
        uint32_t hs = base + HSB + (uint32_t)(j % 3) * 9216u;
#pragma unroll
        for (int ks = 0; ks < 4; ks++) {
            unsigned a0, a1, a2, a3;
            ldsm_x4(a0, a1, a2, a3, ab + (uint32_t)ks * 32u);
#pragma unroll
            for (int dc = 0; dc < 2; dc++) {
                unsigned r0, r1, r2, r3;
                ldsm_x4_t(r0, r1, r2, r3,
                          hs + b_rowoff + (uint32_t)(ks * 16) * 144u + (uint32_t)dc * 32u);
                mma_f16(acc[2 * dc],     a0, a1, a2, a3, r0, r1);
                mma_f16(acc[2 * dc + 1], a0, a1, a2, a3, r2, r3);
            }
        }
    };

    // prologue: two bundles so wait_group(1) at i=0 guarantees E(0)
    stage_E(0, 0);
    cp_commit();
    stage_E(1, 1);
    stage_H(0, 0);
    cp_commit();

    for (int i = 0; i < NTILES; i++) {
        cp_wait1();
        __syncthreads();
        if (i + 1 < NTILES) stage_H(i + 1, (i + 1) % 3);
        if (i + 2 < NTILES) stage_E(i + 2, (i + 2) % 3);
        cp_commit();
        wgen(i);
        if (i > 0) mma_tile(i - 1);
    }
    cp_wait0();
    __syncthreads();
    mma_tile(NTILES - 1);

    // partial denominator reduction -> global (scaled domain)
    Sp[t] = sacc;
    __syncthreads();
    if (t < 64) {
        float s = Sp[t] + Sp[64 + t] + Sp[128 + t] + Sp[192 + t];
        g_den[(z * NH + hd) * NN + n0 + t] = s;
    }

    // raw (scaled) numerator store
    float* dst = g_atts + (size_t)z * NN * FOUT;
    int na = n0 + wn0 + g, nb = na + 8;
    int colbase = hd * DD + wd0 + 2 * tig;
#pragma unroll
    for (int j = 0; j < 4; j++) {
        int col = colbase + 8 * j;
        dst[(size_t)na * FOUT + col]     = acc[j][0];
        dst[(size_t)na * FOUT + col + 1] = acc[j][1];
        dst[(size_t)nb * FOUT + col]     = acc[j][2];
        dst[(size_t)nb * FOUT + col + 1] = acc[j][3];
    }
}

// ---------------- kernel 5: combine + LayerNorm ----------------
__global__ void ln_kernel(const float* __restrict__ gamma,
                          const float* __restrict__ beta,
                          float* __restrict__ out) {
    int wid = threadIdx.x >> 5, lane = threadIdx.x & 31;
    int n = blockIdx.x * 8 + wid;
    int hd = lane >> 3;
    float den = 0.f;
#pragma unroll
    for (int zz = 0; zz < NZ; zz++) den += g_den[(zz * NH + hd) * NN + n];
    float inv = 1.0f / den;
    float4 s0 = make_float4(0.f, 0.f, 0.f, 0.f);
    float4 s1 = make_float4(0.f, 0.f, 0.f, 0.f);
#pragma unroll
    for (int zz = 0; zz < NZ; zz++) {
        const float4* r = (const float4*)(g_atts + (size_t)zz * NN * FOUT + (size_t)n * FOUT);
        float4 u0 = r[lane * 2], u1 = r[lane * 2 + 1];
        s0.x += u0.x; s0.y += u0.y; s0.z += u0.z; s0.w += u0.w;
        s1.x += u1.x; s1.y += u1.y; s1.z += u1.z; s1.w += u1.w;
    }
    float4 v0 = make_float4(s0.x * inv, s0.y * inv, s0.z * inv, s0.w * inv);
    float4 v1 = make_float4(s1.x * inv, s1.y * inv, s1.z * inv, s1.w * inv);
    float s = v0.x + v0.y + v0.z + v0.w + v1.x + v1.y + v1.z + v1.w;
#pragma unroll
    for (int o = 16; o; o >>= 1) s += __shfl_xor_sync(0xffffffffu, s, o);
    float mu = s * (1.0f / 256.0f);
    float d0x = v0.x - mu, d0y = v0.y - mu, d0z = v0.z - mu, d0w = v0.w - mu;
    float d1x = v1.x - mu, d1y = v1.y - mu, d1z = v1.z - mu, d1w = v1.w - mu;
    float vs = d0x * d0x + d0y * d0y + d0z * d0z + d0w * d0w +
               d1x * d1x + d1y * d1y + d1z * d1z + d1w * d1w;
#pragma unroll
    for (int o = 16; o; o >>= 1) vs += __shfl_xor_sync(0xffffffffu, vs, o);
    float rs = rsqrtf(vs * (1.0f / 256.0f) + 1e-5f);
    const float4* gp = (const float4*)gamma;
    const float4* bp = (const float4*)beta;
    float4 gm0 = gp[lane * 2], gm1 = gp[lane * 2 + 1];
    float4 bt0 = bp[lane * 2], bt1 = bp[lane * 2 + 1];
    float4 o0 = make_float4(gm0.x * d0x * rs + bt0.x, gm0.y * d0y * rs + bt0.y,
                            gm0.z * d0z * rs + bt0.z, gm0.w * d0w * rs + bt0.w);
    float4 o1 = make_float4(gm1.x * d1x * rs + bt1.x, gm1.y * d1y * rs + bt1.y,
                            gm1.z * d1z * rs + bt1.z, gm1.w * d1w * rs + bt1.w);
    float4* orow = (float4*)(out + (size_t)n * FOUT);
    orow[lane * 2]     = o0;
    orow[lane * 2 + 1] = o1;
}

// ---------------- launch ----------------
extern "C" void kernel_launch(void* const* d_in, const int* in_sizes, int n_in,
                              void* d_out, int out_size) {
    const float* x     = (const float*)d_in[0];
    const int*   adj   = (const int*)d_in[1];
    const float* W     = (const float*)d_in[2];
    const float* a     = (const float*)d_in[3];
    const float* gamma = (const float*)d_in[4];
    const float* beta  = (const float*)d_in[5];
    float* out = (float*)d_out;

    pack_adj_kernel<<<2048, 256>>>(adj);

    size_t gshmem = GSM * sizeof(float);
    cudaFuncSetAttribute(gemm_h_mma, cudaFuncAttributeMaxDynamicSharedMemorySize,
                         (int)gshmem);
    gemm_h_mma<<<dim3(64, 2), 256, gshmem>>>(x, W);

    prep_kernel<<<512, 256>>>(a);

    cudaFuncSetAttribute(attn_kernel, cudaFuncAttributeMaxDynamicSharedMemorySize,
                         SMEMB);
    attn_kernel<<<dim3(64, NH, NZ), 256, SMEMB>>>();

    ln_kernel<<<512, 256>>>(gamma, beta, out);
}

// round 13
// speedup vs baseline: 1.0400x; 1.0400x over previous
#include <cuda_runtime.h>
#include <cuda_fp16.h>
#include <cstdint>

#define NN   4096
#define FIN  256
#define FOUT 256
#define NH   4
#define DD   64
#define ALPHA 0.2f
#define NZ   4
#define NTILES (NN / NZ / 64)   // 16

// ---------------- device scratch (no allocs allowed) ----------------
__device__ float    g_h [NN * FOUT];
__device__ __half   g_hf[NN * FOUT];
__device__ unsigned g_adjbits[NN * (NN / 32)];
__device__ float    g_A[NH * NN];
__device__ float    g_B[NH * NN];
__device__ float2   g_e12[NH * NN];
__device__ unsigned g_emaxu[NH];
__device__ float    g_atts[NZ * NN * FOUT];
__device__ float    g_den[NZ * NH * NN];

// ---------------- helpers ----------------
__device__ __forceinline__ void cp16(uint32_t dst, const void* src) {
    asm volatile("cp.async.cg.shared.global [%0], [%1], 16;\n" :: "r"(dst), "l"(src));
}
__device__ __forceinline__ void cp8(uint32_t dst, const void* src) {
    asm volatile("cp.async.ca.shared.global [%0], [%1], 8;\n" :: "r"(dst), "l"(src));
}
__device__ __forceinline__ void cp_commit() {
    asm volatile("cp.async.commit_group;\n");
}
__device__ __forceinline__ void cp_wait0() {
    asm volatile("cp.async.wait_group 0;\n");
}
__device__ __forceinline__ void cp_wait1() {
    asm volatile("cp.async.wait_group 1;\n");
}
__device__ __forceinline__ void mma_tf32(float* d, unsigned a0, unsigned a1, unsigned a2,
                                         unsigned a3, unsigned b0, unsigned b1) {
    asm volatile(
        "mma.sync.aligned.m16n8k8.row.col.f32.tf32.tf32.f32 "
        "{%0,%1,%2,%3}, {%4,%5,%6,%7}, {%8,%9}, {%0,%1,%2,%3};\n"
        : "+f"(d[0]), "+f"(d[1]), "+f"(d[2]), "+f"(d[3])
        : "r"(a0), "r"(a1), "r"(a2), "r"(a3), "r"(b0), "r"(b1));
}
__device__ __forceinline__ void mma_f16(float* d, unsigned a0, unsigned a1, unsigned a2,
                                        unsigned a3, unsigned b0, unsigned b1) {
    asm volatile(
        "mma.sync.aligned.m16n8k16.row.col.f32.f16.f16.f32 "
        "{%0,%1,%2,%3}, {%4,%5,%6,%7}, {%8,%9}, {%0,%1,%2,%3};\n"
        : "+f"(d[0]), "+f"(d[1]), "+f"(d[2]), "+f"(d[3])
        : "r"(a0), "r"(a1), "r"(a2), "r"(a3), "r"(b0), "r"(b1));
}
__device__ __forceinline__ void ldsm_x4(unsigned& r0, unsigned& r1, unsigned& r2,
                                        unsigned& r3, uint32_t addr) {
    asm volatile("ldmatrix.sync.aligned.m8n8.x4.shared.b16 {%0,%1,%2,%3}, [%4];"
                 : "=r"(r0), "=r"(r1), "=r"(r2), "=r"(r3) : "r"(addr));
}
__device__ __forceinline__ void ldsm_x4_t(unsigned& r0, unsigned& r1, unsigned& r2,
                                          unsigned& r3, uint32_t addr) {
    asm volatile("ldmatrix.sync.aligned.m8n8.x4.trans.shared.b16 {%0,%1,%2,%3}, [%4];"
                 : "=r"(r0), "=r"(r1), "=r"(r2), "=r"(r3) : "r"(addr));
}
__device__ __forceinline__ float cvt_tf32(float x) {
    unsigned u;
    asm("cvt.rna.tf32.f32 %0, %1;" : "=r"(u) : "f"(x));
    return __uint_as_float(u);
}

// ---------------- kernel 1: pack adj int32 -> bits (+ init emax) ----------------
__global__ void pack_adj_kernel(const int* __restrict__ adj) {
    if (blockIdx.x == 0 && threadIdx.x < NH) g_emaxu[threadIdx.x] = 0u;
    int lane = threadIdx.x & 31;
    size_t gw = (size_t)(blockIdx.x * blockDim.x + threadIdx.x) >> 5;
    const int* base = adj + gw * 1024;
    unsigned myword = 0;
#pragma unroll
    for (int i = 0; i < 32; i++) {
        int v = base[i * 32 + lane];
        unsigned b = __ballot_sync(0xffffffffu, v > 0);
        if (lane == i) myword = b;
    }
    g_adjbits[gw * 32 + lane] = myword;
}

// ---------------- kernel 2: h = x @ W via tf32x3 mma ----------------
#define GXH 0
#define GXL 2304
#define GWH 4608
#define GWL 9088
#define GSM 13568

__global__ __launch_bounds__(256) void gemm_h_mma(const float* __restrict__ x,
                                                  const float* __restrict__ W) {
    extern __shared__ float gs[];
    int t = threadIdx.x;
    int m0 = blockIdx.x * 64;
    int byn0 = blockIdx.y * 128;

    int lane = t & 31, wid = t >> 5;
    int g = lane >> 2, tig = lane & 3;
    int wm0 = (wid & 3) * 16;
    int wn0l = (wid >> 2) * 64;

    int xr = t >> 2, xkc = (t & 3) * 8;
    int wkr = t >> 3, wnb = (t & 7) * 4;

    float4 xa, xb, wreg[4];
    auto ldg_tile = [&](int kt) {
        int k0 = kt * 32;
        const float4* xp = (const float4*)(x + (size_t)(m0 + xr) * FIN + k0 + xkc);
        xa = xp[0];
        xb = xp[1];
#pragma unroll
        for (int c = 0; c < 4; c++)
            wreg[c] = *(const float4*)(W + (size_t)(k0 + wkr) * FOUT + byn0 + wnb + 32 * c);
    };
    auto sts_tile = [&]() {
        float4 h, l;
        h = make_float4(cvt_tf32(xa.x), cvt_tf32(xa.y), cvt_tf32(xa.z), cvt_tf32(xa.w));
        l = make_float4(xa.x - h.x, xa.y - h.y, xa.z - h.z, xa.w - h.w);
        *(float4*)&gs[GXH + xr * 36 + xkc] = h;
        *(float4*)&gs[GXL + xr * 36 + xkc] = l;
        h = make_float4(cvt_tf32(xb.x), cvt_tf32(xb.y), cvt_tf32(xb.z), cvt_tf32(xb.w));
        l = make_float4(xb.x - h.x, xb.y - h.y, xb.z - h.z, xb.w - h.w);
        *(float4*)&gs[GXH + xr * 36 + xkc + 4] = h;
        *(float4*)&gs[GXL + xr * 36 + xkc + 4] = l;
#pragma unroll
        for (int c = 0; c < 4; c++) {
            float4 v = wreg[c];
            h = make_float4(cvt_tf32(v.x), cvt_tf32(v.y), cvt_tf32(v.z), cvt_tf32(v.w));
            l = make_float4(v.x - h.x, v.y - h.y, v.z - h.z, v.w - h.w);
            *(float4*)&gs[GWH + wkr * 140 + wnb + 32 * c] = h;
            *(float4*)&gs[GWL + wkr * 140 + wnb + 32 * c] = l;
        }
    };

    float acc[8][4] = {};
    ldg_tile(0);
    for (int kt = 0; kt < 8; kt++) {
        if (kt) __syncthreads();
        sts_tile();
        __syncthreads();
        if (kt < 7) ldg_tile(kt + 1);
#pragma unroll
        for (int ks = 0; ks < 4; ks++) {
            int k0s = ks * 8;
            unsigned ah0 = __float_as_uint(gs[GXH + (wm0 + g) * 36 + k0s + tig]);
            unsigned ah1 = __float_as_uint(gs[GXH + (wm0 + g + 8) * 36 + k0s + tig]);
            unsigned ah2 = __float_as_uint(gs[GXH + (wm0 + g) * 36 + k0s + tig + 4]);
            unsigned ah3 = __float_as_uint(gs[GXH + (wm0 + g + 8) * 36 + k0s + tig + 4]);
            unsigned al0 = __float_as_uint(gs[GXL + (wm0 + g) * 36 + k0s + tig]);
            unsigned al1 = __float_as_uint(gs[GXL + (wm0 + g + 8) * 36 + k0s + tig]);
            unsigned al2 = __float_as_uint(gs[GXL + (wm0 + g) * 36 + k0s + tig + 4]);
            unsigned al3 = __float_as_uint(gs[GXL + (wm0 + g + 8) * 36 + k0s + tig + 4]);
#pragma unroll
            for (int j = 0; j < 8; j++) {
                int bo = (k0s + tig) * 140 + wn0l + 8 * j + g;
                int bo4 = (k0s + tig + 4) * 140 + wn0l + 8 * j + g;
                unsigned bh0 = __float_as_uint(gs[GWH + bo]);
                unsigned bh1 = __float_as_uint(gs[GWH + bo4]);
                unsigned bl0 = __float_as_uint(gs[GWL + bo]);
                unsigned bl1 = __float_as_uint(gs[GWL + bo4]);
                mma_tf32(acc[j], ah0, ah1, ah2, ah3, bh0, bh1);
                mma_tf32(acc[j], ah0, ah1, ah2, ah3, bl0, bl1);
                mma_tf32(acc[j], al0, al1, al2, al3, bh0, bh1);
            }
        }
    }

    int r0 = m0 + wm0 + g, r1 = r0 + 8;
#pragma unroll
    for (int j = 0; j < 8; j++) {
        int cg = byn0 + wn0l + 8 * j + 2 * tig;
        *(float2*)(g_h + (size_t)r0 * FOUT + cg) = make_float2(acc[j][0], acc[j][1]);
        *(float2*)(g_h + (size_t)r1 * FOUT + cg) = make_float2(acc[j][2], acc[j][3]);
        *(__half2*)(g_hf + (size_t)r0 * FOUT + cg) = __floats2half2_rn(acc[j][0], acc[j][1]);
        *(__half2*)(g_hf + (size_t)r1 * FOUT + cg) = __floats2half2_rn(acc[j][2], acc[j][3]);
    }
}

// ---------------- kernel 3: si/sj dots + exp tables + head max ----------------
__global__ void prep_kernel(const float* __restrict__ a) {
    __shared__ float a_s[128];
    int t = threadIdx.x;
    if (t < 128) a_s[t] = a[t];
    __syncthreads();
    int wid  = t >> 5, lane = t & 31;
    int n    = blockIdx.x * 8 + wid;
    int head = lane >> 3;
    int sub  = lane & 7;
    const float4* hrow = (const float4*)(g_h + (size_t)n * FOUT);
    float psi = 0.f, psj = 0.f;
#pragma unroll
    for (int v = 0; v < 2; v++) {
        float4 hv = hrow[lane * 2 + v];
        int db = sub * 8 + v * 4;
        psi += hv.x * a_s[db]      + hv.y * a_s[db + 1]      + hv.z * a_s[db + 2]      + hv.w * a_s[db + 3];
        psj += hv.x * a_s[64 + db] + hv.y * a_s[64 + db + 1] + hv.z * a_s[64 + db + 2] + hv.w * a_s[64 + db + 3];
    }
#pragma unroll
    for (int off = 4; off; off >>= 1) {
        psi += __shfl_down_sync(0xffffffffu, psi, off);
        psj += __shfl_down_sync(0xffffffffu, psj, off);
    }
    if (sub == 0) {
        int idx = head * NN + n;
        float e1 = expf(psj);
        g_A[idx]   = expf(psi);
        g_B[idx]   = expf(ALPHA * psi);
        g_e12[idx] = make_float2(e1, expf(ALPHA * psj));
        atomicMax(&g_emaxu[head], __float_as_uint(e1));
    }
}

// ---------------- kernel 4: fused attention (fp16 mma, k-split warps) ----------------
// smem BYTE offsets
#define HSB    0        // H tiles, 3 buffers x 9216
#define WTB    27648    // Wt, 2 buffers x 9216 (combine area reuses this at epilogue)
#define E12B   46080    // float2[64], 3 buffers x 512
#define ADJB   47616    // uint[128], 3 buffers x 512
#define SPB    49152    // float[256]
#define SMEMB  50176

// grid (64, NH, NZ). 256 thr, 3 CTA/SM.
__global__ __launch_bounds__(256, 3) void attn_kernel() {
    extern __shared__ char smc[];
    float* Sp = (float*)(smc + SPB);

    int t  = threadIdx.x;
    int hd = blockIdx.y;
    int n0 = blockIdx.x * 64;
    int z  = blockIdx.z;
    int mz0 = z * (NN / NZ);

    uint32_t base = (uint32_t)__cvta_generic_to_shared(smc);

    int nl = t & 63, mc = t >> 6;
    int lane = t & 31, wid = t >> 5;
    int g   = lane >> 2;
    int tig = lane & 3;
    // k-split warp layout: 2n x 2d x 2m, each warp 32n x 32d x 32m
    int kw  = wid >> 2;              // m-half
    int wn0 = (wid & 1) * 32;        // warp n offset
    int wd0 = ((wid >> 1) & 1) * 32; // warp d offset
    int wm0 = kw * 32;               // warp m offset within 64-tile
    float acc[2][2][2][4] = {};      // [rb][dc][e][4]
    float sacc = 0.f;

    float An = g_A[hd * NN + n0 + nl];
    float Bn = g_B[hd * NN + n0 + nl];
    {
        float E1x = __uint_as_float(g_emaxu[hd]);
        float E2x = __powf(E1x, ALPHA);
        float s = 16384.f / fmaxf(An * E1x, Bn * E2x);
        An *= s;
        Bn *= s;
    }

    int lrow = (lane & 7) + (lane & 8);
    int lhi8 = (lane >> 4) * 8;

    auto stage_H = [&](int mt, int b) {
        int m0 = mz0 + mt * 64;
        uint32_t hb = base + HSB + (uint32_t)b * 9216u;
#pragma unroll
        for (int r = 0; r < 2; r++) {
            int li = t + r * 256;
            int mi = li >> 3, c = li & 7;
            cp16(hb + (uint32_t)(mi * 144 + c * 16),
                 g_hf + (size_t)(m0 + mi) * FOUT + hd * DD + c * 8);
        }
    };
    auto stage_E = [&](int mt, int b) {
        int m0 = mz0 + mt * 64;
        if (t < 32)
            cp16(base + E12B + (uint32_t)b * 512u + (uint32_t)t * 16u,
                 (const char*)(g_e12 + hd * NN + m0) + t * 16);
        if (t >= 64 && t < 128) {
            int rr = t - 64;
            cp8(base + ADJB + (uint32_t)b * 512u + (uint32_t)rr * 8u,
                g_adjbits + (size_t)(n0 + rr) * (NN / 32) + (m0 >> 5));
        }
    };

    auto wgen = [&](int i) {
        int pe = i % 3;
        int wb = i & 1;
        unsigned word = ((unsigned*)(smc + ADJB + pe * 512))[nl * 2 + (mc >> 1)]
                        >> ((mc & 1) * 16);
        const float4* e4 = (const float4*)(smc + E12B + pe * 512 + mc * 128);
        unsigned wp[8];
#pragma unroll
        for (int i2 = 0; i2 < 16; i2 += 4) {
            float4 ea = e4[(i2 >> 1)];
            float4 eb = e4[(i2 >> 1) + 1];
            float w0 = fmaxf(An * ea.x, Bn * ea.y);
            float w1 = fmaxf(An * ea.z, Bn * ea.w);
            float w2 = fmaxf(An * eb.x, Bn * eb.y);
            float w3 = fmaxf(An * eb.z, Bn * eb.w);
            w0 = ((word >> (i2 + 0)) & 1u) ? w0 : 0.f;
            w1 = ((word >> (i2 + 1)) & 1u) ? w1 : 0.f;
            w2 = ((word >> (i2 + 2)) & 1u) ? w2 : 0.f;
            w3 = ((word >> (i2 + 3)) & 1u) ? w3 : 0.f;
            sacc += (w0 + w1) + (w2 + w3);
            __half2 h01 = __floats2half2_rn(w0, w1);
            __half2 h23 = __floats2half2_rn(w2, w3);
            wp[(i2 >> 1)]     = *(unsigned*)&h01;
            wp[(i2 >> 1) + 1] = *(unsigned*)&h23;
        }
        uint4* wr = (uint4*)(smc + WTB + wb * 9216 + nl * 144 + mc * 32);
        wr[0] = make_uint4(wp[0], wp[1], wp[2], wp[3]);
        wr[1] = make_uint4(wp[4], wp[5], wp[6], wp[7]);
    };

    auto mma_tile = [&](int j) {
        uint32_t ab = base + WTB + (uint32_t)(j & 1) * 9216u;
        uint32_t hs = base + HSB + (uint32_t)(j % 3) * 9216u;
#pragma unroll
        for (int ks = 0; ks < 2; ks++) {
            int mk = wm0 + ks * 16;
            unsigned a0[4], a1[4];
            ldsm_x4(a0[0], a0[1], a0[2], a0[3],
                    ab + (uint32_t)(wn0 + lrow) * 144u + (uint32_t)(mk + lhi8) * 2u);
            ldsm_x4(a1[0], a1[1], a1[2], a1[3],
                    ab + (uint32_t)(wn0 + 16 + lrow) * 144u + (uint32_t)(mk + lhi8) * 2u);
#pragma unroll
            for (int dc = 0; dc < 2; dc++) {
                unsigned r0, r1, r2, r3;
                ldsm_x4_t(r0, r1, r2, r3,
                          hs + (uint32_t)(mk + lrow) * 144u +
                          (uint32_t)(wd0 + dc * 16 + lhi8) * 2u);
                mma_f16(acc[0][dc][0], a0[0], a0[1], a0[2], a0[3], r0, r1);
                mma_f16(acc[0][dc][1], a0[0], a0[1], a0[2], a0[3], r2, r3);
                mma_f16(acc[1][dc][0], a1[0], a1[1], a1[2], a1[3], r0, r1);
                mma_f16(acc[1][dc][1], a1[0], a1[1], a1[2], a1[3], r2, r3);
            }
        }
    };

    // prologue: two bundles so wait_group(1) at i=0 guarantees E(0)
    stage_E(0, 0);
    cp_commit();
    stage_E(1, 1);
    stage_H(0, 0);
    cp_commit();

    for (int i = 0; i < NTILES; i++) {
        cp_wait1();
        __syncthreads();
        if (i + 1 < NTILES) stage_H(i + 1, (i + 1) % 3);
        if (i + 2 < NTILES) stage_E(i + 2, (i + 2) % 3);
        cp_commit();
        wgen(i);
        if (i > 0) mma_tile(i - 1);
    }
    cp_wait0();
    __syncthreads();
    mma_tile(NTILES - 1);

    // partial denominator reduction -> global (scaled domain)
    Sp[t] = sacc;
    __syncthreads();   // also orders last mma's Wt reads before combine-area overwrite
    if (t < 64) {
        float s = Sp[t] + Sp[64 + t] + Sp[128 + t] + Sp[192 + t];
        g_den[(z * NH + hd) * NN + n0 + t] = s;
    }

    // combine the two m-halves through smem, then store numerators
    float* comb = (float*)(smc + WTB);   // [64][68]
    if (kw == 1) {
#pragma unroll
        for (int rb = 0; rb < 2; rb++)
#pragma unroll
            for (int dc = 0; dc < 2; dc++)
#pragma unroll
                for (int e = 0; e < 2; e++) {
                    int row = wn0 + rb * 16 + g;
                    int col = wd0 + dc * 16 + e * 8 + 2 * tig;
                    *(float2*)&comb[row * 68 + col] =
                        make_float2(acc[rb][dc][e][0], acc[rb][dc][e][1]);
                    *(float2*)&comb[(row + 8) * 68 + col] =
                        make_float2(acc[rb][dc][e][2], acc[rb][dc][e][3]);
                }
    }
    __syncthreads();
    if (kw == 0) {
        float* dst = g_atts + (size_t)z * NN * FOUT;
#pragma unroll
        for (int rb = 0; rb < 2; rb++)
#pragma unroll
            for (int dc = 0; dc < 2; dc++)
#pragma unroll
                for (int e = 0; e < 2; e++) {
                    int row = wn0 + rb * 16 + g;
                    int col = wd0 + dc * 16 + e * 8 + 2 * tig;
                    float2 p0 = *(float2*)&comb[row * 68 + col];
                    float2 p1 = *(float2*)&comb[(row + 8) * 68 + col];
                    *(float2*)&dst[(size_t)(n0 + row) * FOUT + hd * DD + col] =
                        make_float2(acc[rb][dc][e][0] + p0.x, acc[rb][dc][e][1] + p0.y);
                    *(float2*)&dst[(size_t)(n0 + row + 8) * FOUT + hd * DD + col] =
                        make_float2(acc[rb][dc][e][2] + p1.x, acc[rb][dc][e][3] + p1.y);
                }
    }
}

// ---------------- kernel 5: combine + LayerNorm ----------------
__global__ void ln_kernel(const float* __restrict__ gamma,
                          const float* __restrict__ beta,
                          float* __restrict__ out) {
    int wid = threadIdx.x >> 5, lane = threadIdx.x & 31;
    int n = blockIdx.x * 8 + wid;
    int hd = lane >> 3;
    float den = 0.f;
#pragma unroll
    for (int zz = 0; zz < NZ; zz++) den += g_den[(zz * NH + hd) * NN + n];
    float inv = 1.0f / den;
    float4 s0 = make_float4(0.f, 0.f, 0.f, 0.f);
    float4 s1 = make_float4(0.f, 0.f, 0.f, 0.f);
#pragma unroll
    for (int zz = 0; zz < NZ; zz++) {
        const float4* r = (const float4*)(g_atts + (size_t)zz * NN * FOUT + (size_t)n * FOUT);
        float4 u0 = r[lane * 2], u1 = r[lane * 2 + 1];
        s0.x += u0.x; s0.y += u0.y; s0.z += u0.z; s0.w += u0.w;
        s1.x += u1.x; s1.y += u1.y; s1.z += u1.z; s1.w += u1.w;
    }
    float4 v0 = make_float4(s0.x * inv, s0.y * inv, s0.z * inv, s0.w * inv);
    float4 v1 = make_float4(s1.x * inv, s1.y * inv, s1.z * inv, s1.w * inv);
    float s = v0.x + v0.y + v0.z + v0.w + v1.x + v1.y + v1.z + v1.w;
#pragma unroll
    for (int o = 16; o; o >>= 1) s += __shfl_xor_sync(0xffffffffu, s, o);
    float mu = s * (1.0f / 256.0f);
    float d0x = v0.x - mu, d0y = v0.y - mu, d0z = v0.z - mu, d0w = v0.w - mu;
    float d1x = v1.x - mu, d1y = v1.y - mu, d1z = v1.z - mu, d1w = v1.w - mu;
    float vs = d0x * d0x + d0y * d0y + d0z * d0z + d0w * d0w +
               d1x * d1x + d1y * d1y + d1z * d1z + d1w * d1w;
#pragma unroll
    for (int o = 16; o; o >>= 1) vs += __shfl_xor_sync(0xffffffffu, vs, o);
    float rs = rsqrtf(vs * (1.0f / 256.0f) + 1e-5f);
    const float4* gp = (const float4*)gamma;
    const float4* bp = (const float4*)beta;
    float4 gm0 = gp[lane * 2], gm1 = gp[lane * 2 + 1];
    float4 bt0 = bp[lane * 2], bt1 = bp[lane * 2 + 1];
    float4 o0 = make_float4(gm0.x * d0x * rs + bt0.x, gm0.y * d0y * rs + bt0.y,
                            gm0.z * d0z * rs + bt0.z, gm0.w * d0w * rs + bt0.w);
    float4 o1 = make_float4(gm1.x * d1x * rs + bt1.x, gm1.y * d1y * rs + bt1.y,
                            gm1.z * d1z * rs + bt1.z, gm1.w * d1w * rs + bt1.w);
    float4* orow = (float4*)(out + (size_t)n * FOUT);
    orow[lane * 2]     = o0;
    orow[lane * 2 + 1] = o1;
}

// ---------------- launch ----------------
extern "C" void kernel_launch(void* const* d_in, const int* in_sizes, int n_in,
                              void* d_out, int out_size) {
    const float* x     = (const float*)d_in[0];
    const int*   adj   = (const int*)d_in[1];
    const float* W     = (const float*)d_in[2];
    const float* a     = (const float*)d_in[3];
    const float* gamma = (const float*)d_in[4];
    const float* beta  = (const float*)d_in[5];
    float* out = (float*)d_out;

    pack_adj_kernel<<<2048, 256>>>(adj);

    size_t gshmem = GSM * sizeof(float);
    cudaFuncSetAttribute(gemm_h_mma, cudaFuncAttributeMaxDynamicSharedMemorySize,
                         (int)gshmem);
    gemm_h_mma<<<dim3(64, 2), 256, gshmem>>>(x, W);

    prep_kernel<<<512, 256>>>(a);

    cudaFuncSetAttribute(attn_kernel, cudaFuncAttributeMaxDynamicSharedMemorySize,
                         SMEMB);
    attn_kernel<<<dim3(64, NH, NZ), 256, SMEMB>>>();

    ln_kernel<<<512, 256>>>(gamma, beta, out);
}

// round 14
// speedup vs baseline: 1.0732x; 1.0319x over previous
#include <cuda_runtime.h>
#include <cuda_fp16.h>
#include <cstdint>

#define NN   4096
#define FIN  256
#define FOUT 256
#define NH   4
#define DD   64
#define ALPHA 0.2f
#define NZ   4
#define NTILES (NN / NZ / 64)   // 16

// ---------------- device scratch (no allocs allowed) ----------------
__device__ float    g_h [NN * FOUT];
__device__ __half   g_hf[NN * FOUT];
__device__ unsigned g_adjbits[NN * (NN / 32)];
__device__ float    g_A[NH * NN];
__device__ float    g_B[NH * NN];
__device__ float2   g_e12[NH * NN];
__device__ unsigned g_emaxu[NH];
__device__ float    g_atts[NZ * NN * FOUT];
__device__ float    g_den[NZ * NH * NN];

// ---------------- helpers ----------------
__device__ __forceinline__ void cp16(uint32_t dst, const void* src) {
    asm volatile("cp.async.cg.shared.global [%0], [%1], 16;\n" :: "r"(dst), "l"(src));
}
__device__ __forceinline__ void cp8(uint32_t dst, const void* src) {
    asm volatile("cp.async.ca.shared.global [%0], [%1], 8;\n" :: "r"(dst), "l"(src));
}
__device__ __forceinline__ void cp_commit() {
    asm volatile("cp.async.commit_group;\n");
}
__device__ __forceinline__ void cp_wait0() {
    asm volatile("cp.async.wait_group 0;\n");
}
__device__ __forceinline__ void cp_wait1() {
    asm volatile("cp.async.wait_group 1;\n");
}
__device__ __forceinline__ void mma_tf32(float* d, unsigned a0, unsigned a1, unsigned a2,
                                         unsigned a3, unsigned b0, unsigned b1) {
    asm volatile(
        "mma.sync.aligned.m16n8k8.row.col.f32.tf32.tf32.f32 "
        "{%0,%1,%2,%3}, {%4,%5,%6,%7}, {%8,%9}, {%0,%1,%2,%3};\n"
        : "+f"(d[0]), "+f"(d[1]), "+f"(d[2]), "+f"(d[3])
        : "r"(a0), "r"(a1), "r"(a2), "r"(a3), "r"(b0), "r"(b1));
}
__device__ __forceinline__ void mma_f16(float* d, unsigned a0, unsigned a1, unsigned a2,
                                        unsigned a3, unsigned b0, unsigned b1) {
    asm volatile(
        "mma.sync.aligned.m16n8k16.row.col.f32.f16.f16.f32 "
        "{%0,%1,%2,%3}, {%4,%5,%6,%7}, {%8,%9}, {%0,%1,%2,%3};\n"
        : "+f"(d[0]), "+f"(d[1]), "+f"(d[2]), "+f"(d[3])
        : "r"(a0), "r"(a1), "r"(a2), "r"(a3), "r"(b0), "r"(b1));
}
__device__ __forceinline__ void ldsm_x4(unsigned& r0, unsigned& r1, unsigned& r2,
                                        unsigned& r3, uint32_t addr) {
    asm volatile("ldmatrix.sync.aligned.m8n8.x4.shared.b16 {%0,%1,%2,%3}, [%4];"
                 : "=r"(r0), "=r"(r1), "=r"(r2), "=r"(r3) : "r"(addr));
}
__device__ __forceinline__ void ldsm_x4_t(unsigned& r0, unsigned& r1, unsigned& r2,
                                          unsigned& r3, uint32_t addr) {
    asm volatile("ldmatrix.sync.aligned.m8n8.x4.trans.shared.b16 {%0,%1,%2,%3}, [%4];"
                 : "=r"(r0), "=r"(r1), "=r"(r2), "=r"(r3) : "r"(addr));
}
__device__ __forceinline__ float cvt_tf32(float x) {
    unsigned u;
    asm("cvt.rna.tf32.f32 %0, %1;" : "=r"(u) : "f"(x));
    return __uint_as_float(u);
}

// ---------------- kernel 1: FUSED pack(adj) || gemm_h (role split) ----------------
// CTAs [0,128): gemm (needs smem, 1/SM, starts immediately).
// CTAs [128,2176): pack (no smem, co-schedules around gemm).
#define GXH 0
#define GXL 2304
#define GWH 4608
#define GWL 9088
#define GSM 13568   // floats (54272 B)

__global__ void fused_pre_kernel(const int* __restrict__ adj,
                                 const float* __restrict__ x,
                                 const float* __restrict__ W) {
    if (blockIdx.x >= 128) {
        // ---------------- pack role ----------------
        int pbid = blockIdx.x - 128;
        if (pbid == 0 && threadIdx.x < NH) g_emaxu[threadIdx.x] = 0u;
        int lane = threadIdx.x & 31;
        size_t gw = (size_t)(pbid * 256 + threadIdx.x) >> 5;
        const int* base = adj + gw * 1024;
        unsigned myword = 0;
#pragma unroll
        for (int i = 0; i < 32; i++) {
            int v = base[i * 32 + lane];
            unsigned b = __ballot_sync(0xffffffffu, v > 0);
            if (lane == i) myword = b;
        }
        g_adjbits[gw * 32 + lane] = myword;
        return;
    }

    // ---------------- gemm role (tf32x3 mma) ----------------
    extern __shared__ float gs[];
    int t = threadIdx.x;
    int m0 = (blockIdx.x & 63) * 64;
    int byn0 = (blockIdx.x >> 6) * 128;

    int lane = t & 31, wid = t >> 5;
    int g = lane >> 2, tig = lane & 3;
    int wm0 = (wid & 3) * 16;
    int wn0l = (wid >> 2) * 64;

    int xr = t >> 2, xkc = (t & 3) * 8;
    int wkr = t >> 3, wnb = (t & 7) * 4;

    float4 xa, xb, wreg[4];
    auto ldg_tile = [&](int kt) {
        int k0 = kt * 32;
        const float4* xp = (const float4*)(x + (size_t)(m0 + xr) * FIN + k0 + xkc);
        xa = xp[0];
        xb = xp[1];
#pragma unroll
        for (int c = 0; c < 4; c++)
            wreg[c] = *(const float4*)(W + (size_t)(k0 + wkr) * FOUT + byn0 + wnb + 32 * c);
    };
    auto sts_tile = [&]() {
        float4 h, l;
        h = make_float4(cvt_tf32(xa.x), cvt_tf32(xa.y), cvt_tf32(xa.z), cvt_tf32(xa.w));
        l = make_float4(xa.x - h.x, xa.y - h.y, xa.z - h.z, xa.w - h.w);
        *(float4*)&gs[GXH + xr * 36 + xkc] = h;
        *(float4*)&gs[GXL + xr * 36 + xkc] = l;
        h = make_float4(cvt_tf32(xb.x), cvt_tf32(xb.y), cvt_tf32(xb.z), cvt_tf32(xb.w));
        l = make_float4(xb.x - h.x, xb.y - h.y, xb.z - h.z, xb.w - h.w);
        *(float4*)&gs[GXH + xr * 36 + xkc + 4] = h;
        *(float4*)&gs[GXL + xr * 36 + xkc + 4] = l;
#pragma unroll
        for (int c = 0; c < 4; c++) {
            float4 v = wreg[c];
            h = make_float4(cvt_tf32(v.x), cvt_tf32(v.y), cvt_tf32(v.z), cvt_tf32(v.w));
            l = make_float4(v.x - h.x, v.y - h.y, v.z - h.z, v.w - h.w);
            *(float4*)&gs[GWH + wkr * 140 + wnb + 32 * c] = h;
            *(float4*)&gs[GWL + wkr * 140 + wnb + 32 * c] = l;
        }
    };

    float acc[8][4] = {};
    ldg_tile(0);
    for (int kt = 0; kt < 8; kt++) {
        if (kt) __syncthreads();
        sts_tile();
        __syncthreads();
        if (kt < 7) ldg_tile(kt + 1);
#pragma unroll
        for (int ks = 0; ks < 4; ks++) {
            int k0s = ks * 8;
            unsigned ah0 = __float_as_uint(gs[GXH + (wm0 + g) * 36 + k0s + tig]);
            unsigned ah1 = __float_as_uint(gs[GXH + (wm0 + g + 8) * 36 + k0s + tig]);
            unsigned ah2 = __float_as_uint(gs[GXH + (wm0 + g) * 36 + k0s + tig + 4]);
            unsigned ah3 = __float_as_uint(gs[GXH + (wm0 + g + 8) * 36 + k0s + tig + 4]);
            unsigned al0 = __float_as_uint(gs[GXL + (wm0 + g) * 36 + k0s + tig]);
            unsigned al1 = __float_as_uint(gs[GXL + (wm0 + g + 8) * 36 + k0s + tig]);
            unsigned al2 = __float_as_uint(gs[GXL + (wm0 + g) * 36 + k0s + tig + 4]);
            unsigned al3 = __float_as_uint(gs[GXL + (wm0 + g + 8) * 36 + k0s + tig + 4]);
#pragma unroll
            for (int j = 0; j < 8; j++) {
                int bo = (k0s + tig) * 140 + wn0l + 8 * j + g;
                int bo4 = (k0s + tig + 4) * 140 + wn0l + 8 * j + g;
                unsigned bh0 = __float_as_uint(gs[GWH + bo]);
                unsigned bh1 = __float_as_uint(gs[GWH + bo4]);
                unsigned bl0 = __float_as_uint(gs[GWL + bo]);
                unsigned bl1 = __float_as_uint(gs[GWL + bo4]);
                mma_tf32(acc[j], ah0, ah1, ah2, ah3, bh0, bh1);
                mma_tf32(acc[j], ah0, ah1, ah2, ah3, bl0, bl1);
                mma_tf32(acc[j], al0, al1, al2, al3, bh0, bh1);
            }
        }
    }

    int r0 = m0 + wm0 + g, r1 = r0 + 8;
#pragma unroll
    for (int j = 0; j < 8; j++) {
        int cg = byn0 + wn0l + 8 * j + 2 * tig;
        *(float2*)(g_h + (size_t)r0 * FOUT + cg) = make_float2(acc[j][0], acc[j][1]);
        *(float2*)(g_h + (size_t)r1 * FOUT + cg) = make_float2(acc[j][2], acc[j][3]);
        *(__half2*)(g_hf + (size_t)r0 * FOUT + cg) = __floats2half2_rn(acc[j][0], acc[j][1]);
        *(__half2*)(g_hf + (size_t)r1 * FOUT + cg) = __floats2half2_rn(acc[j][2], acc[j][3]);
    }
}

// ---------------- kernel 3: si/sj dots + exp tables + head max ----------------
__global__ void prep_kernel(const float* __restrict__ a) {
    __shared__ float a_s[128];
    int t = threadIdx.x;
    if (t < 128) a_s[t] = a[t];
    __syncthreads();
    int wid  = t >> 5, lane = t & 31;
    int n    = blockIdx.x * 8 + wid;
    int head = lane >> 3;
    int sub  = lane & 7;
    const float4* hrow = (const float4*)(g_h + (size_t)n * FOUT);
    float psi = 0.f, psj = 0.f;
#pragma unroll
    for (int v = 0; v < 2; v++) {
        float4 hv = hrow[lane * 2 + v];
        int db = sub * 8 + v * 4;
        psi += hv.x * a_s[db]      + hv.y * a_s[db + 1]      + hv.z * a_s[db + 2]      + hv.w * a_s[db + 3];
        psj += hv.x * a_s[64 + db] + hv.y * a_s[64 + db + 1] + hv.z * a_s[64 + db + 2] + hv.w * a_s[64 + db + 3];
    }
#pragma unroll
    for (int off = 4; off; off >>= 1) {
        psi += __shfl_down_sync(0xffffffffu, psi, off);
        psj += __shfl_down_sync(0xffffffffu, psj, off);
    }
    if (sub == 0) {
        int idx = head * NN + n;
        float e1 = expf(psj);
        g_A[idx]   = expf(psi);
        g_B[idx]   = expf(ALPHA * psi);
        g_e12[idx] = make_float2(e1, expf(ALPHA * psj));
        atomicMax(&g_emaxu[head], __float_as_uint(e1));
    }
}

// ---------------- kernel 4: fused attention (fp16 mma, k-split warps) ----------------
// smem BYTE offsets
#define HSB    0        // H tiles, 3 buffers x 9216
#define WTB    27648    // Wt, 2 buffers x 9216 (combine area reuses this at epilogue)
#define E12B   46080    // float2[64], 3 buffers x 512
#define ADJB   47616    // uint[128], 3 buffers x 512
#define SPB    49152    // float[256]
#define SMEMB  50176

// grid (64, NH, NZ). 256 thr, 3 CTA/SM.
__global__ __launch_bounds__(256, 3) void attn_kernel() {
    extern __shared__ char smc[];
    float* Sp = (float*)(smc + SPB);

    int t  = threadIdx.x;
    int hd = blockIdx.y;
    int n0 = blockIdx.x * 64;
    int z  = blockIdx.z;
    int mz0 = z * (NN / NZ);

    uint32_t base = (uint32_t)__cvta_generic_to_shared(smc);

    int nl = t & 63, mc = t >> 6;
    int lane = t & 31, wid = t >> 5;
    int g   = lane >> 2;
    int tig = lane & 3;
    // k-split warp layout: 2n x 2d x 2m, each warp 32n x 32d x 32m
    int kw  = wid >> 2;              // m-half
    int wn0 = (wid & 1) * 32;        // warp n offset
    int wd0 = ((wid >> 1) & 1) * 32; // warp d offset
    int wm0 = kw * 32;               // warp m offset within 64-tile
    float acc[2][2][2][4] = {};      // [rb][dc][e][4]
    float sacc = 0.f;

    float An = g_A[hd * NN + n0 + nl];
    float Bn = g_B[hd * NN + n0 + nl];
    {
        float E1x = __uint_as_float(g_emaxu[hd]);
        float E2x = __powf(E1x, ALPHA);
        float s = 16384.f / fmaxf(An * E1x, Bn * E2x);
        An *= s;
        Bn *= s;
    }

    int lrow = (lane & 7) + (lane & 8);
    int lhi8 = (lane >> 4) * 8;

    auto stage_H = [&](int mt, int b) {
        int m0 = mz0 + mt * 64;
        uint32_t hb = base + HSB + (uint32_t)b * 9216u;
#pragma unroll
        for (int r = 0; r < 2; r++) {
            int li = t + r * 256;
            int mi = li >> 3, c = li & 7;
            cp16(hb + (uint32_t)(mi * 144 + c * 16),
                 g_hf + (size_t)(m0 + mi) * FOUT + hd * DD + c * 8);
        }
    };
    auto stage_E = [&](int mt, int b) {
        int m0 = mz0 + mt * 64;
        if (t < 32)
            cp16(base + E12B + (uint32_t)b * 512u + (uint32_t)t * 16u,
                 (const char*)(g_e12 + hd * NN + m0) + t * 16);
        if (t >= 64 && t < 128) {
            int rr = t - 64;
            cp8(base + ADJB + (uint32_t)b * 512u + (uint32_t)rr * 8u,
                g_adjbits + (size_t)(n0 + rr) * (NN / 32) + (m0 >> 5));
        }
    };

    auto wgen = [&](int i) {
        int pe = i % 3;
        int wb = i & 1;
        unsigned word = ((unsigned*)(smc + ADJB + pe * 512))[nl * 2 + (mc >> 1)]
                        >> ((mc & 1) * 16);
        const float4* e4 = (const float4*)(smc + E12B + pe * 512 + mc * 128);
        unsigned wp[8];
#pragma unroll
        for (int i2 = 0; i2 < 16; i2 += 4) {
            float4 ea = e4[(i2 >> 1)];
            float4 eb = e4[(i2 >> 1) + 1];
            float w0 = fmaxf(An * ea.x, Bn * ea.y);
            float w1 = fmaxf(An * ea.z, Bn * ea.w);
            float w2 = fmaxf(An * eb.x, Bn * eb.y);
            float w3 = fmaxf(An * eb.z, Bn * eb.w);
            w0 = ((word >> (i2 + 0)) & 1u) ? w0 : 0.f;
            w1 = ((word >> (i2 + 1)) & 1u) ? w1 : 0.f;
            w2 = ((word >> (i2 + 2)) & 1u) ? w2 : 0.f;
            w3 = ((word >> (i2 + 3)) & 1u) ? w3 : 0.f;
            sacc += (w0 + w1) + (w2 + w3);
            __half2 h01 = __floats2half2_rn(w0, w1);
            __half2 h23 = __floats2half2_rn(w2, w3);
            wp[(i2 >> 1)]     = *(unsigned*)&h01;
            wp[(i2 >> 1) + 1] = *(unsigned*)&h23;
        }
        uint4* wr = (uint4*)(smc + WTB + wb * 9216 + nl * 144 + mc * 32);
        wr[0] = make_uint4(wp[0], wp[1], wp[2], wp[3]);
        wr[1] = make_uint4(wp[4], wp[5], wp[6], wp[7]);
    };

    auto mma_tile = [&](int j) {
        uint32_t ab = base + WTB + (uint32_t)(j & 1) * 9216u;
        uint32_t hs = base + HSB + (uint32_t)(j % 3) * 9216u;
#pragma unroll
        for (int ks = 0; ks < 2; ks++) {
            int mk = wm0 + ks * 16;
            unsigned a0[4], a1[4];
            ldsm_x4(a0[0], a0[1], a0[2], a0[3],
                    ab + (uint32_t)(wn0 + lrow) * 144u + (uint32_t)(mk + lhi8) * 2u);
            ldsm_x4(a1[0], a1[1], a1[2], a1[3],
                    ab + (uint32_t)(wn0 + 16 + lrow) * 144u + (uint32_t)(mk + lhi8) * 2u);
#pragma unroll
            for (int dc = 0; dc < 2; dc++) {
                unsigned r0, r1, r2, r3;
                ldsm_x4_t(r0, r1, r2, r3,
                          hs + (uint32_t)(mk + lrow) * 144u +
                          (uint32_t)(wd0 + dc * 16 + lhi8) * 2u);
                mma_f16(acc[0][dc][0], a0[0], a0[1], a0[2], a0[3], r0, r1);
                mma_f16(acc[0][dc][1], a0[0], a0[1], a0[2], a0[3], r2, r3);
                mma_f16(acc[1][dc][0], a1[0], a1[1], a1[2], a1[3], r0, r1);
                mma_f16(acc[1][dc][1], a1[0], a1[1], a1[2], a1[3], r2, r3);
            }
        }
    };

    // prologue: two bundles so wait_group(1) at i=0 guarantees E(0)
    stage_E(0, 0);
    cp_commit();
    stage_E(1, 1);
    stage_H(0, 0);
    cp_commit();

    for (int i = 0; i < NTILES; i++) {
        cp_wait1();
        __syncthreads();
        if (i + 1 < NTILES) stage_H(i + 1, (i + 1) % 3);
        if (i + 2 < NTILES) stage_E(i + 2, (i + 2) % 3);
        cp_commit();
        wgen(i);
        if (i > 0) mma_tile(i - 1);
    }
    cp_wait0();
    __syncthreads();
    mma_tile(NTILES - 1);

    // partial denominator reduction -> global (scaled domain)
    Sp[t] = sacc;
    __syncthreads();   // also orders last mma's Wt reads before combine-area overwrite
    if (t < 64) {
        float s = Sp[t] + Sp[64 + t] + Sp[128 + t] + Sp[192 + t];
        g_den[(z * NH + hd) * NN + n0 + t] = s;
    }

    // combine the two m-halves through smem, then store numerators
    float* comb = (float*)(smc + WTB);   // [64][68]
    if (kw == 1) {
#pragma unroll
        for (int rb = 0; rb < 2; rb++)
#pragma unroll
            for (int dc = 0; dc < 2; dc++)
#pragma unroll
                for (int e = 0; e < 2; e++) {
                    int row = wn0 + rb * 16 + g;
                    int col = wd0 + dc * 16 + e * 8 + 2 * tig;
                    *(float2*)&comb[row * 68 + col] =
                        make_float2(acc[rb][dc][e][0], acc[rb][dc][e][1]);
                    *(float2*)&comb[(row + 8) * 68 + col] =
                        make_float2(acc[rb][dc][e][2], acc[rb][dc][e][3]);
                }
    }
    __syncthreads();
    if (kw == 0) {
        float* dst = g_atts + (size_t)z * NN * FOUT;
#pragma unroll
        for (int rb = 0; rb < 2; rb++)
#pragma unroll
            for (int dc = 0; dc < 2; dc++)
#pragma unroll
                for (int e = 0; e < 2; e++) {
                    int row = wn0 + rb * 16 + g;
                    int col = wd0 + dc * 16 + e * 8 + 2 * tig;
                    float2 p0 = *(float2*)&comb[row * 68 + col];
                    float2 p1 = *(float2*)&comb[(row + 8) * 68 + col];
                    *(float2*)&dst[(size_t)(n0 + row) * FOUT + hd * DD + col] =
                        make_float2(acc[rb][dc][e][0] + p0.x, acc[rb][dc][e][1] + p0.y);
                    *(float2*)&dst[(size_t)(n0 + row + 8) * FOUT + hd * DD + col] =
                        make_float2(acc[rb][dc][e][2] + p1.x, acc[rb][dc][e][3] + p1.y);
                }
    }
}

// ---------------- kernel 5: combine + LayerNorm ----------------
__global__ void ln_kernel(const float* __restrict__ gamma,
                          const float* __restrict__ beta,
                          float* __restrict__ out) {
    int wid = threadIdx.x >> 5, lane = threadIdx.x & 31;
    int n = blockIdx.x * 8 + wid;
    int hd = lane >> 3;
    float den = 0.f;
#pragma unroll
    for (int zz = 0; zz < NZ; zz++) den += g_den[(zz * NH + hd) * NN + n];
    float inv = 1.0f / den;
    float4 s0 = make_float4(0.f, 0.f, 0.f, 0.f);
    float4 s1 = make_float4(0.f, 0.f, 0.f, 0.f);
#pragma unroll
    for (int zz = 0; zz < NZ; zz++) {
        const float4* r = (const float4*)(g_atts + (size_t)zz * NN * FOUT + (size_t)n * FOUT);
        float4 u0 = r[lane * 2], u1 = r[lane * 2 + 1];
        s0.x += u0.x; s0.y += u0.y; s0.z += u0.z; s0.w += u0.w;
        s1.x += u1.x; s1.y += u1.y; s1.z += u1.z; s1.w += u1.w;
    }
    float4 v0 = make_float4(s0.x * inv, s0.y * inv, s0.z * inv, s0.w * inv);
    float4 v1 = make_float4(s1.x * inv, s1.y * inv, s1.z * inv, s1.w * inv);
    float s = v0.x + v0.y + v0.z + v0.w + v1.x + v1.y + v1.z + v1.w;
#pragma unroll
    for (int o = 16; o; o >>= 1) s += __shfl_xor_sync(0xffffffffu, s, o);
    float mu = s * (1.0f / 256.0f);
    float d0x = v0.x - mu, d0y = v0.y - mu, d0z = v0.z - mu, d0w = v0.w - mu;
    float d1x = v1.x - mu, d1y = v1.y - mu, d1z = v1.z - mu, d1w = v1.w - mu;
    float vs = d0x * d0x + d0y * d0y + d0z * d0z + d0w * d0w +
               d1x * d1x + d1y * d1y + d1z * d1z + d1w * d1w;
#pragma unroll
    for (int o = 16; o; o >>= 1) vs += __shfl_xor_sync(0xffffffffu, vs, o);
    float rs = rsqrtf(vs * (1.0f / 256.0f) + 1e-5f);
    const float4* gp = (const float4*)gamma;
    const float4* bp = (const float4*)beta;
    float4 gm0 = gp[lane * 2], gm1 = gp[lane * 2 + 1];
    float4 bt0 = bp[lane * 2], bt1 = bp[lane * 2 + 1];
    float4 o0 = make_float4(gm0.x * d0x * rs + bt0.x, gm0.y * d0y * rs + bt0.y,
                            gm0.z * d0z * rs + bt0.z, gm0.w * d0w * rs + bt0.w);
    float4 o1 = make_float4(gm1.x * d1x * rs + bt1.x, gm1.y * d1y * rs + bt1.y,
                            gm1.z * d1z * rs + bt1.z, gm1.w * d1w * rs + bt1.w);
    float4* orow = (float4*)(out + (size_t)n * FOUT);
    orow[lane * 2]     = o0;
    orow[lane * 2 + 1] = o1;
}

// ---------------- launch ----------------
extern "C" void kernel_launch(void* const* d_in, const int* in_sizes, int n_in,
                              void* d_out, int out_size) {
    const float* x     = (const float*)d_in[0];
    const int*   adj   = (const int*)d_in[1];
    const float* W     = (const float*)d_in[2];
    const float* a     = (const float*)d_in[3];
    const float* gamma = (const float*)d_in[4];
    const float* beta  = (const float*)d_in[5];
    float* out = (float*)d_out;

    size_t gshmem = GSM * sizeof(float);   // 54272 B
    cudaFuncSetAttribute(fused_pre_kernel, cudaFuncAttributeMaxDynamicSharedMemorySize,
                         (int)gshmem);
    fused_pre_kernel<<<128 + 2048, 256, gshmem>>>(adj, x, W);

    prep_kernel<<<512, 256>>>(a);

    cudaFuncSetAttribute(attn_kernel, cudaFuncAttributeMaxDynamicSharedMemorySize,
                         SMEMB);
    attn_kernel<<<dim3(64, NH, NZ), 256, SMEMB>>>();

    ln_kernel<<<512, 256>>>(gamma, beta, out);
}

// round 17
// speedup vs baseline: 1.0833x; 1.0094x over previous
#include <cuda_runtime.h>
#include <cuda_fp16.h>
#include <cstdint>

#define NN   4096
#define FIN  256
#define FOUT 256
#define NH   4
#define DD   64
#define ALPHA 0.2f
#define NZ   4
#define NTILES (NN / NZ / 64)   // 16

// ---------------- device scratch (no allocs allowed) ----------------
__device__ float    g_h [NN * FOUT];
__device__ __half   g_hf[NN * FOUT];
__device__ unsigned g_adjbits[NN * (NN / 32)];
__device__ float    g_A[NH * NN];
__device__ float    g_B[NH * NN];
__device__ float2   g_e12[NH * NN];
__device__ unsigned g_emaxu[NH];
__device__ __half   g_atts[NZ * NN * FOUT];   // fp16 split numerators (scaled domain)
__device__ float    g_den[NZ * NH * NN];

// ---------------- helpers ----------------
__device__ __forceinline__ void cp16(uint32_t dst, const void* src) {
    asm volatile("cp.async.cg.shared.global [%0], [%1], 16;\n" :: "r"(dst), "l"(src));
}
__device__ __forceinline__ void cp8(uint32_t dst, const void* src) {
    asm volatile("cp.async.ca.shared.global [%0], [%1], 8;\n" :: "r"(dst), "l"(src));
}
__device__ __forceinline__ void cp_commit() {
    asm volatile("cp.async.commit_group;\n");
}
__device__ __forceinline__ void cp_wait0() {
    asm volatile("cp.async.wait_group 0;\n");
}
__device__ __forceinline__ void cp_wait1() {
    asm volatile("cp.async.wait_group 1;\n");
}
__device__ __forceinline__ void mma_tf32(float* d, unsigned a0, unsigned a1, unsigned a2,
                                         unsigned a3, unsigned b0, unsigned b1) {
    asm volatile(
        "mma.sync.aligned.m16n8k8.row.col.f32.tf32.tf32.f32 "
        "{%0,%1,%2,%3}, {%4,%5,%6,%7}, {%8,%9}, {%0,%1,%2,%3};\n"
        : "+f"(d[0]), "+f"(d[1]), "+f"(d[2]), "+f"(d[3])
        : "r"(a0), "r"(a1), "r"(a2), "r"(a3), "r"(b0), "r"(b1));
}
__device__ __forceinline__ void mma_f16(float* d, unsigned a0, unsigned a1, unsigned a2,
                                        unsigned a3, unsigned b0, unsigned b1) {
    asm volatile(
        "mma.sync.aligned.m16n8k16.row.col.f32.f16.f16.f32 "
        "{%0,%1,%2,%3}, {%4,%5,%6,%7}, {%8,%9}, {%0,%1,%2,%3};\n"
        : "+f"(d[0]), "+f"(d[1]), "+f"(d[2]), "+f"(d[3])
        : "r"(a0), "r"(a1), "r"(a2), "r"(a3), "r"(b0), "r"(b1));
}
__device__ __forceinline__ void ldsm_x4(unsigned& r0, unsigned& r1, unsigned& r2,
                                        unsigned& r3, uint32_t addr) {
    asm volatile("ldmatrix.sync.aligned.m8n8.x4.shared.b16 {%0,%1,%2,%3}, [%4];"
                 : "=r"(r0), "=r"(r1), "=r"(r2), "=r"(r3) : "r"(addr));
}
__device__ __forceinline__ void ldsm_x4_t(unsigned& r0, unsigned& r1, unsigned& r2,
                                          unsigned& r3, uint32_t addr) {
    asm volatile("ldmatrix.sync.aligned.m8n8.x4.trans.shared.b16 {%0,%1,%2,%3}, [%4];"
                 : "=r"(r0), "=r"(r1), "=r"(r2), "=r"(r3) : "r"(addr));
}
__device__ __forceinline__ float cvt_tf32(float x) {
    unsigned u;
    asm("cvt.rna.tf32.f32 %0, %1;" : "=r"(u) : "f"(x));
    return __uint_as_float(u);
}

// ---------------- kernel 1: FUSED pack(adj) || gemm_h (role split) ----------------
#define GXH 0
#define GXL 2304
#define GWH 4608
#define GWL 9088
#define GSM 13568   // floats (54272 B)

__global__ void fused_pre_kernel(const int* __restrict__ adj,
                                 const float* __restrict__ x,
                                 const float* __restrict__ W) {
    if (blockIdx.x >= 128) {
        // ---------------- pack role ----------------
        int pbid = blockIdx.x - 128;
        if (pbid == 0 && threadIdx.x < NH) g_emaxu[threadIdx.x] = 0u;
        int lane = threadIdx.x & 31;
        size_t gw = (size_t)(pbid * 256 + threadIdx.x) >> 5;
        const int* base = adj + gw * 1024;
        unsigned myword = 0;
#pragma unroll
        for (int i = 0; i < 32; i++) {
            int v = base[i * 32 + lane];
            unsigned b = __ballot_sync(0xffffffffu, v > 0);
            if (lane == i) myword = b;
        }
        g_adjbits[gw * 32 + lane] = myword;
        return;
    }

    // ---------------- gemm role (tf32x3 mma) ----------------
    extern __shared__ float gs[];
    int t = threadIdx.x;
    int m0 = (blockIdx.x & 63) * 64;
    int byn0 = (blockIdx.x >> 6) * 128;

    int lane = t & 31, wid = t >> 5;
    int g = lane >> 2, tig = lane & 3;
    int wm0 = (wid & 3) * 16;
    int wn0l = (wid >> 2) * 64;

    int xr = t >> 2, xkc = (t & 3) * 8;
    int wkr = t >> 3, wnb = (t & 7) * 4;

    float4 xa, xb, wreg[4];
    auto ldg_tile = [&](int kt) {
        int k0 = kt * 32;
        const float4* xp = (const float4*)(x + (size_t)(m0 + xr) * FIN + k0 + xkc);
        xa = xp[0];
        xb = xp[1];
#pragma unroll
        for (int c = 0; c < 4; c++)
            wreg[c] = *(const float4*)(W + (size_t)(k0 + wkr) * FOUT + byn0 + wnb + 32 * c);
    };
    auto sts_tile = [&]() {
        float4 h, l;
        h = make_float4(cvt_tf32(xa.x), cvt_tf32(xa.y), cvt_tf32(xa.z), cvt_tf32(xa.w));
        l = make_float4(xa.x - h.x, xa.y - h.y, xa.z - h.z, xa.w - h.w);
        *(float4*)&gs[GXH + xr * 36 + xkc] = h;
        *(float4*)&gs[GXL + xr * 36 + xkc] = l;
        h = make_float4(cvt_tf32(xb.x), cvt_tf32(xb.y), cvt_tf32(xb.z), cvt_tf32(xb.w));
        l = make_float4(xb.x - h.x, xb.y - h.y, xb.z - h.z, xb.w - h.w);
        *(float4*)&gs[GXH + xr * 36 + xkc + 4] = h;
        *(float4*)&gs[GXL + xr * 36 + xkc + 4] = l;
#pragma unroll
        for (int c = 0; c < 4; c++) {
            float4 v = wreg[c];
            h = make_float4(cvt_tf32(v.x), cvt_tf32(v.y), cvt_tf32(v.z), cvt_tf32(v.w));
            l = make_float4(v.x - h.x, v.y - h.y, v.z - h.z, v.w - h.w);
            *(float4*)&gs[GWH + wkr * 140 + wnb + 32 * c] = h;
            *(float4*)&gs[GWL + wkr * 140 + wnb + 32 * c] = l;
        }
    };

    float acc[8][4] = {};
    ldg_tile(0);
    for (int kt = 0; kt < 8; kt++) {
        if (kt) __syncthreads();
        sts_tile();
        __syncthreads();
        if (kt < 7) ldg_tile(kt + 1);
#pragma unroll
        for (int ks = 0; ks < 4; ks++) {
            int k0s = ks * 8;
            unsigned ah0 = __float_as_uint(gs[GXH + (wm0 + g) * 36 + k0s + tig]);
            unsigned ah1 = __float_as_uint(gs[GXH + (wm0 + g + 8) * 36 + k0s + tig]);
            unsigned ah2 = __float_as_uint(gs[GXH + (wm0 + g) * 36 + k0s + tig + 4]);
            unsigned ah3 = __float_as_uint(gs[GXH + (wm0 + g + 8) * 36 + k0s + tig + 4]);
            unsigned al0 = __float_as_uint(gs[GXL + (wm0 + g) * 36 + k0s + tig]);
            unsigned al1 = __float_as_uint(gs[GXL + (wm0 + g + 8) * 36 + k0s + tig]);
            unsigned al2 = __float_as_uint(gs[GXL + (wm0 + g) * 36 + k0s + tig + 4]);
            unsigned al3 = __float_as_uint(gs[GXL + (wm0 + g + 8) * 36 + k0s + tig + 4]);
#pragma unroll
            for (int j = 0; j < 8; j++) {
                int bo = (k0s + tig) * 140 + wn0l + 8 * j + g;
                int bo4 = (k0s + tig + 4) * 140 + wn0l + 8 * j + g;
                unsigned bh0 = __float_as_uint(gs[GWH + bo]);
                unsigned bh1 = __float_as_uint(gs[GWH + bo4]);
                unsigned bl0 = __float_as_uint(gs[GWL + bo]);
                unsigned bl1 = __float_as_uint(gs[GWL + bo4]);
                mma_tf32(acc[j], ah0, ah1, ah2, ah3, bh0, bh1);
                mma_tf32(acc[j], ah0, ah1, ah2, ah3, bl0, bl1);
                mma_tf32(acc[j], al0, al1, al2, al3, bh0, bh1);
            }
        }
    }

    int r0 = m0 + wm0 + g, r1 = r0 + 8;
#pragma unroll
    for (int j = 0; j < 8; j++) {
        int cg = byn0 + wn0l + 8 * j + 2 * tig;
        *(float2*)(g_h + (size_t)r0 * FOUT + cg) = make_float2(acc[j][0], acc[j][1]);
        *(float2*)(g_h + (size_t)r1 * FOUT + cg) = make_float2(acc[j][2], acc[j][3]);
        *(__half2*)(g_hf + (size_t)r0 * FOUT + cg) = __floats2half2_rn(acc[j][0], acc[j][1]);
        *(__half2*)(g_hf + (size_t)r1 * FOUT + cg) = __floats2half2_rn(acc[j][2], acc[j][3]);
    }
}

// ---------------- kernel 3: si/sj dots + exp tables + head max ----------------
__global__ void prep_kernel(const float* __restrict__ a) {
    __shared__ float a_s[128];
    int t = threadIdx.x;
    if (t < 128) a_s[t] = a[t];
    __syncthreads();
    int wid  = t >> 5, lane = t & 31;
    int n    = blockIdx.x * 8 + wid;
    int head = lane >> 3;
    int sub  = lane & 7;
    const float4* hrow = (const float4*)(g_h + (size_t)n * FOUT);
    float psi = 0.f, psj = 0.f;
#pragma unroll
    for (int v = 0; v < 2; v++) {
        float4 hv = hrow[lane * 2 + v];
        int db = sub * 8 + v * 4;
        psi += hv.x * a_s[db]      + hv.y * a_s[db + 1]      + hv.z * a_s[db + 2]      + hv.w * a_s[db + 3];
        psj += hv.x * a_s[64 + db] + hv.y * a_s[64 + db + 1] + hv.z * a_s[64 + db + 2] + hv.w * a_s[64 + db + 3];
    }
#pragma unroll
    for (int off = 4; off; off >>= 1) {
        psi += __shfl_down_sync(0xffffffffu, psi, off);
        psj += __shfl_down_sync(0xffffffffu, psj, off);
    }
    if (sub == 0) {
        int idx = head * NN + n;
        float e1 = expf(psj);
        g_A[idx]   = expf(psi);
        g_B[idx]   = expf(ALPHA * psi);
        g_e12[idx] = make_float2(e1, expf(ALPHA * psj));
        atomicMax(&g_emaxu[head], __float_as_uint(e1));
    }
}

// ---------------- kernel 4: fused attention (fp16 mma, k-split warps) ----------------
// smem BYTE offsets
#define HSB    0        // H tiles, 3 buffers x 9216
#define WTB    27648    // Wt, 2 buffers x 9216 (combine area reuses this at epilogue)
#define E12B   46080    // float2[64], 3 buffers x 512
#define ADJB   47616    // uint[128], 3 buffers x 512
#define SPB    49152    // float[256]
#define SMEMB  50176

// grid (64, NH, NZ). 256 thr, 3 CTA/SM.
__global__ __launch_bounds__(256, 3) void attn_kernel() {
    extern __shared__ char smc[];
    float* Sp = (float*)(smc + SPB);

    int t  = threadIdx.x;
    int hd = blockIdx.y;
    int n0 = blockIdx.x * 64;
    int z  = blockIdx.z;
    int mz0 = z * (NN / NZ);

    uint32_t base = (uint32_t)__cvta_generic_to_shared(smc);

    int nl = t & 63, mc = t >> 6;
    int lane = t & 31, wid = t >> 5;
    int g   = lane >> 2;
    int tig = lane & 3;
    // k-split warp layout: 2n x 2d x 2m, each warp 32n x 32d x 32m
    int kw  = wid >> 2;              // m-half
    int wn0 = (wid & 1) * 32;        // warp n offset
    int wd0 = ((wid >> 1) & 1) * 32; // warp d offset
    int wm0 = kw * 32;               // warp m offset within 64-tile
    float acc[2][2][2][4] = {};      // [rb][dc][e][4]
    float sacc = 0.f;

    float An = g_A[hd * NN + n0 + nl];
    float Bn = g_B[hd * NN + n0 + nl];
    {
        float E1x = __uint_as_float(g_emaxu[hd]);
        float E2x = __powf(E1x, ALPHA);
        float s = 4.0f / fmaxf(An * E1x, Bn * E2x);   // w <= 4: slice numerators fit fp16
        An *= s;
        Bn *= s;
    }

    int lrow = (lane & 7) + (lane & 8);
    int lhi8 = (lane >> 4) * 8;

    auto stage_H = [&](int mt, int b) {
        int m0 = mz0 + mt * 64;
        uint32_t hb = base + HSB + (uint32_t)b * 9216u;
#pragma unroll
        for (int r = 0; r < 2; r++) {
            int li = t + r * 256;
            int mi = li >> 3, c = li & 7;
            cp16(hb + (uint32_t)(mi * 144 + c * 16),
                 g_hf + (size_t)(m0 + mi) * FOUT + hd * DD + c * 8);
        }
    };
    auto stage_E = [&](int mt, int b) {
        int m0 = mz0 + mt * 64;
        if (t < 32)
            cp16(base + E12B + (uint32_t)b * 512u + (uint32_t)t * 16u,
                 (const char*)(g_e12 + hd * NN + m0) + t * 16);
        if (t >= 64 && t < 128) {
            int rr = t - 64;
            cp8(base + ADJB + (uint32_t)b * 512u + (uint32_t)rr * 8u,
                g_adjbits + (size_t)(n0 + rr) * (NN / 32) + (m0 >> 5));
        }
    };

    auto wgen = [&](int i) {
        int pe = i % 3;
        int wb = i & 1;
        unsigned word = ((unsigned*)(smc + ADJB + pe * 512))[nl * 2 + (mc >> 1)]
                        >> ((mc & 1) * 16);
        const float4* e4 = (const float4*)(smc + E12B + pe * 512 + mc * 128);
        unsigned wp[8];
#pragma unroll
        for (int i2 = 0; i2 < 16; i2 += 4) {
            float4 ea = e4[(i2 >> 1)];
            float4 eb = e4[(i2 >> 1) + 1];
            float w0 = fmaxf(An * ea.x, Bn * ea.y);
            float w1 = fmaxf(An * ea.z, Bn * ea.w);
            float w2 = fmaxf(An * eb.x, Bn * eb.y);
            float w3 = fmaxf(An * eb.z, Bn * eb.w);
            w0 = ((word >> (i2 + 0)) & 1u) ? w0 : 0.f;
            w1 = ((word >> (i2 + 1)) & 1u) ? w1 : 0.f;
            w2 = ((word >> (i2 + 2)) & 1u) ? w2 : 0.f;
            w3 = ((word >> (i2 + 3)) & 1u) ? w3 : 0.f;
            sacc += (w0 + w1) + (w2 + w3);
            __half2 h01 = __floats2half2_rn(w0, w1);
            __half2 h23 = __floats2half2_rn(w2, w3);
            wp[(i2 >> 1)]     = *(unsigned*)&h01;
            wp[(i2 >> 1) + 1] = *(unsigned*)&h23;
        }
        uint4* wr = (uint4*)(smc + WTB + wb * 9216 + nl * 144 + mc * 32);
        wr[0] = make_uint4(wp[0], wp[1], wp[2], wp[3]);
        wr[1] = make_uint4(wp[4], wp[5], wp[6], wp[7]);
    };

    auto mma_tile = [&](int j) {
        uint32_t ab = base + WTB + (uint32_t)(j & 1) * 9216u;
        uint32_t hs = base + HSB + (uint32_t)(j % 3) * 9216u;
#pragma unroll
        for (int ks = 0; ks < 2; ks++) {
            int mk = wm0 + ks * 16;
            unsigned a0[4], a1[4];
            ldsm_x4(a0[0], a0[1], a0[2], a0[3],
                    ab + (uint32_t)(wn0 + lrow) * 144u + (uint32_t)(mk + lhi8) * 2u);
            ldsm_x4(a1[0], a1[1], a1[2], a1[3],
                    ab + (uint32_t)(wn0 + 16 + lrow) * 144u + (uint32_t)(mk + lhi8) * 2u);
#pragma unroll
            for (int dc = 0; dc < 2; dc++) {
                unsigned r0, r1, r2, r3;
                ldsm_x4_t(r0, r1, r2, r3,
                          hs + (uint32_t)(mk + lrow) * 144u +
                          (uint32_t)(wd0 + dc * 16 + lhi8) * 2u);
                mma_f16(acc[0][dc][0], a0[0], a0[1], a0[2], a0[3], r0, r1);
                mma_f16(acc[0][dc][1], a0[0], a0[1], a0[2], a0[3], r2, r3);
                mma_f16(acc[1][dc][0], a1[0], a1[1], a1[2], a1[3], r0, r1);
                mma_f16(acc[1][dc][1], a1[0], a1[1], a1[2], a1[3], r2, r3);
            }
        }
    };

    // prologue: two bundles so wait_group(1) at i=0 guarantees E(0)
    stage_E(0, 0);
    cp_commit();
    stage_E(1, 1);
    stage_H(0, 0);
    cp_commit();

    for (int i = 0; i < NTILES; i++) {
        cp_wait1();
        __syncthreads();
        if (i + 1 < NTILES) stage_H(i + 1, (i + 1) % 3);
        if (i + 2 < NTILES) stage_E(i + 2, (i + 2) % 3);
        cp_commit();
        wgen(i);
        if (i > 0) mma_tile(i - 1);
    }
    cp_wait0();
    __syncthreads();
    mma_tile(NTILES - 1);

    // partial denominator reduction -> global (scaled domain)
    Sp[t] = sacc;
    __syncthreads();   // also orders last mma's Wt reads before combine-area overwrite
    if (t < 64) {
        float s = Sp[t] + Sp[64 + t] + Sp[128 + t] + Sp[192 + t];
        g_den[(z * NH + hd) * NN + n0 + t] = s;
    }

    // combine the two m-halves through smem, then store numerators as fp16
    float* comb = (float*)(smc + WTB);   // [64][68]
    if (kw == 1) {
#pragma unroll
        for (int rb = 0; rb < 2; rb++)
#pragma unroll
            for (int dc = 0; dc < 2; dc++)
#pragma unroll
                for (int e = 0; e < 2; e++) {
                    int row = wn0 + rb * 16 + g;
                    int col = wd0 + dc * 16 + e * 8 + 2 * tig;
                    *(float2*)&comb[row * 68 + col] =
                        make_float2(acc[rb][dc][e][0], acc[rb][dc][e][1]);
                    *(float2*)&comb[(row + 8) * 68 + col] =
                        make_float2(acc[rb][dc][e][2], acc[rb][dc][e][3]);
                }
    }
    __syncthreads();
    if (kw == 0) {
        __half* dst = g_atts + (size_t)z * NN * FOUT;
#pragma unroll
        for (int rb = 0; rb < 2; rb++)
#pragma unroll
            for (int dc = 0; dc < 2; dc++)
#pragma unroll
                for (int e = 0; e < 2; e++) {
                    int row = wn0 + rb * 16 + g;
                    int col = wd0 + dc * 16 + e * 8 + 2 * tig;
                    float2 p0 = *(float2*)&comb[row * 68 + col];
                    float2 p1 = *(float2*)&comb[(row + 8) * 68 + col];
                    *(__half2*)&dst[(size_t)(n0 + row) * FOUT + hd * DD + col] =
                        __floats2half2_rn(acc[rb][dc][e][0] + p0.x,
                                          acc[rb][dc][e][1] + p0.y);
                    *(__half2*)&dst[(size_t)(n0 + row + 8) * FOUT + hd * DD + col] =
                        __floats2half2_rn(acc[rb][dc][e][2] + p1.x,
                                          acc[rb][dc][e][3] + p1.y);
                }
    }
}

// ---------------- kernel 5: combine + LayerNorm ----------------
__global__ void ln_kernel(const float* __restrict__ gamma,
                          const float* __restrict__ beta,
                          float* __restrict__ out) {
    int wid = threadIdx.x >> 5, lane = threadIdx.x & 31;
    int n = blockIdx.x * 8 + wid;
    int hd = lane >> 3;
    float den = 0.f;
#pragma unroll
    for (int zz = 0; zz < NZ; zz++) den += g_den[(zz * NH + hd) * NN + n];
    float inv = 1.0f / den;
    float4 s0 = make_float4(0.f, 0.f, 0.f, 0.f);
    float4 s1 = make_float4(0.f, 0.f, 0.f, 0.f);
#pragma unroll
    for (int zz = 0; zz < NZ; zz++) {
        const uint4* rp = (const uint4*)(g_atts + (size_t)zz * NN * FOUT + (size_t)n * FOUT);
        uint4 u = rp[lane];
        float2 f0 = __half22float2(*(__half2*)&u.x);
        float2 f1 = __half22float2(*(__half2*)&u.y);
        float2 f2 = __half22float2(*(__half2*)&u.z);
        float2 f3 = __half22float2(*(__half2*)&u.w);
        s0.x += f0.x; s0.y += f0.y; s0.z += f1.x; s0.w += f1.y;
        s1.x += f2.x; s1.y += f2.y; s1.z += f3.x; s1.w += f3.y;
    }
    float4 v0 = make_float4(s0.x * inv, s0.y * inv, s0.z * inv, s0.w * inv);
    float4 v1 = make_float4(s1.x * inv, s1.y * inv, s1.z * inv, s1.w * inv);
    float s = v0.x + v0.y + v0.z + v0.w + v1.x + v1.y + v1.z + v1.w;
#pragma unroll
    for (int o = 16; o; o >>= 1) s += __shfl_xor_sync(0xffffffffu, s, o);
    float mu = s * (1.0f / 256.0f);
    float d0x = v0.x - mu, d0y = v0.y - mu, d0z = v0.z - mu, d0w = v0.w - mu;
    float d1x = v1.x - mu, d1y = v1.y - mu, d1z = v1.z - mu, d1w = v1.w - mu;
    float vs = d0x * d0x + d0y * d0y + d0z * d0z + d0w * d0w +
               d1x * d1x + d1y * d1y + d1z * d1z + d1w * d1w;
#pragma unroll
    for (int o = 16; o; o >>= 1) vs += __shfl_xor_sync(0xffffffffu, vs, o);
    float rs = rsqrtf(vs * (1.0f / 256.0f) + 1e-5f);
    // lane covers 8 consecutive cols starting at lane*8
    const float4* gp = (const float4*)gamma;
    const float4* bp = (const float4*)beta;
    float4 gm0 = gp[lane * 2], gm1 = gp[lane * 2 + 1];
    float4 bt0 = bp[lane * 2], bt1 = bp[lane * 2 + 1];
    float4 o0 = make_float4(gm0.x * d0x * rs + bt0.x, gm0.y * d0y * rs + bt0.y,
                            gm0.z * d0z * rs + bt0.z, gm0.w * d0w * rs + bt0.w);
    float4 o1 = make_float4(gm1.x * d1x * rs + bt1.x, gm1.y * d1y * rs + bt1.y,
                            gm1.z * d1z * rs + bt1.z, gm1.w * d1w * rs + bt1.w);
    float4* orow = (float4*)(out + (size_t)n * FOUT);
    orow[lane * 2]     = o0;
    orow[lane * 2 + 1] = o1;
}

// ---------------- launch ----------------
extern "C" void kernel_launch(void* const* d_in, const int* in_sizes, int n_in,
                              void* d_out, int out_size) {
    const float* x     = (const float*)d_in[0];
    const int*   adj   = (const int*)d_in[1];
    const float* W     = (const float*)d_in[2];
    const float* a     = (const float*)d_in[3];
    const float* gamma = (const float*)d_in[4];
    const float* beta  = (const float*)d_in[5];
    float* out = (float*)d_out;

    size_t gshmem = GSM * sizeof(float);   // 54272 B
    cudaFuncSetAttribute(fused_pre_kernel, cudaFuncAttributeMaxDynamicSharedMemorySize,
                         (int)gshmem);
    fused_pre_kernel<<<128 + 2048, 256, gshmem>>>(adj, x, W);

    prep_kernel<<<512, 256>>>(a);

    cudaFuncSetAttribute(attn_kernel, cudaFuncAttributeMaxDynamicSharedMemorySize,
                         SMEMB);
    attn_kernel<<<dim3(64, NH, NZ), 256, SMEMB>>>();

    ln_kernel<<<512, 256>>>(gamma, beta, out);
}